// round 2
// baseline (speedup 1.0000x reference)
#include <cuda_runtime.h>

static constexpr int kNH = 50000;
static constexpr int kNO = 50000;
static constexpr int kE  = 500000;
static constexpr int kD  = 256;
static constexpr int kL  = 8;
static constexpr int kB  = 512;
static constexpr int kC  = 117;

// ---------------- device scratch (static, no runtime alloc) ----------------
__device__ float g_h0[kNH * kD];
__device__ float g_h1[kNH * kD];
__device__ float g_o0[kNO * kD];
__device__ float g_o1[kNO * kD];
__device__ float g_agg[kNH * kD];

__device__ float g_aSho[kNH], g_aDoh[kNH], g_aDho[kNO], g_aSoh[kNO];

__device__ float g_vsrc[2 * kL * kD];
__device__ float g_vdst[2 * kL * kD];
__device__ float g_cedge[2 * kL * 2];

__device__ int g_off[2 * (kNH + 1)];
__device__ int g_eid[2 * kE];
__device__ int g_cursor[2 * kNH];

__device__ float g_hsum[kB * kD], g_osum[kB * kD], g_esum[kB * 32];
__device__ float g_hcnt[kB], g_ocnt[kB], g_ecnt[kB];

// ---------------- small precompute: vsrc = Wsrc@asrc, vdst = Wdst@adst, cedge = Wedge@aedge
__global__ void k_precompute(
    const float* __restrict__ Wsrc0, const float* __restrict__ asrc0,
    const float* __restrict__ Wdst0, const float* __restrict__ adst0,
    const float* __restrict__ Wedge0, const float* __restrict__ aedge0,
    const float* __restrict__ Wsrc1, const float* __restrict__ asrc1,
    const float* __restrict__ Wdst1, const float* __restrict__ adst1,
    const float* __restrict__ Wedge1, const float* __restrict__ aedge1)
{
    int rel = blockIdx.x / kL;
    int l   = blockIdx.x % kL;
    const float* Wsrc  = rel ? Wsrc1  : Wsrc0;
    const float* asrc  = rel ? asrc1  : asrc0;
    const float* Wdst  = rel ? Wdst1  : Wdst0;
    const float* adst  = rel ? adst1  : adst0;
    const float* Wedge = rel ? Wedge1 : Wedge0;
    const float* aedge = rel ? aedge1 : aedge0;

    int i = threadIdx.x;  // 0..255
    float s1 = 0.f, s2 = 0.f;
    const float* wsr = Wsrc + (long)l * kD * kD + (long)i * kD;
    const float* wdr = Wdst + (long)l * kD * kD + (long)i * kD;
    const float* as  = asrc + l * kD;
    const float* ad  = adst + l * kD;
    for (int j = 0; j < kD; j++) { s1 += wsr[j] * as[j]; s2 += wdr[j] * ad[j]; }
    g_vsrc[(rel * kL + l) * kD + i] = s1;
    g_vdst[(rel * kL + l) * kD + i] = s2;
    if (i < 2) {
        float c = 0.f;
        const float* we = Wedge + (long)l * 2 * kD + (long)i * kD;
        const float* ae = aedge + l * kD;
        for (int j = 0; j < kD; j++) c += we[j] * ae[j];
        g_cedge[(rel * kL + l) * 2 + i] = c;
    }
}

// ---------------- CSR build ----------------
__global__ void k_hist(const int* __restrict__ dst, int* __restrict__ cnt)
{
    int e = blockIdx.x * blockDim.x + threadIdx.x;
    if (e < kE) atomicAdd(&cnt[dst[e]], 1);
}

__global__ void k_scan(int* __restrict__ cnt, int* __restrict__ off, int N, int total)
{
    __shared__ int ssum[1024];
    int t = threadIdx.x;
    int chunk = (N + 1023) / 1024;
    int b0 = t * chunk;
    int b1 = min(N, b0 + chunk);
    int s = 0;
    for (int i = b0; i < b1; i++) s += cnt[i];
    ssum[t] = s;
    __syncthreads();
    for (int ofs = 1; ofs < 1024; ofs <<= 1) {
        int v = (t >= ofs) ? ssum[t - ofs] : 0;
        __syncthreads();
        ssum[t] += v;
        __syncthreads();
    }
    int pre = (t == 0) ? 0 : ssum[t - 1];
    for (int i = b0; i < b1; i++) {
        int c = cnt[i];
        off[i] = pre;
        cnt[i] = pre;  // cursor starts at segment begin
        pre += c;
    }
    if (t == 1023) off[N] = total;
}

__global__ void k_scatter(const int* __restrict__ dst, int* __restrict__ cur,
                          int* __restrict__ eid)
{
    int e = blockIdx.x * blockDim.x + threadIdx.x;
    if (e >= kE) return;
    int p = atomicAdd(&cur[dst[e]], 1);
    eid[p] = e;
}

// ---------------- fused dual matvec: a1 = x@v1, a2 = x@v2 ----------------
__global__ void k_matvec2(const float* __restrict__ x,
                          const float* __restrict__ v1, const float* __restrict__ v2,
                          float* __restrict__ a1, float* __restrict__ a2, int N)
{
    int w = (blockIdx.x * blockDim.x + threadIdx.x) >> 5;
    int lane = threadIdx.x & 31;
    if (w >= N) return;
    const float* xr = x + (long)w * kD;
    float s1 = 0.f, s2 = 0.f;
#pragma unroll
    for (int k = 0; k < 8; k++) {
        float xv = xr[lane + 32 * k];
        s1 += xv * v1[lane + 32 * k];
        s2 += xv * v2[lane + 32 * k];
    }
#pragma unroll
    for (int o = 16; o > 0; o >>= 1) {
        s1 += __shfl_xor_sync(0xffffffffu, s1, o);
        s2 += __shfl_xor_sync(0xffffffffu, s2, o);
    }
    if (lane == 0) { a1[w] = s1; a2[w] = s2; }
}

// ---------------- per-dst segment softmax + weighted gather-aggregate ----------------
__global__ void k_aggregate(const int* __restrict__ off, const int* __restrict__ eid,
                            const int* __restrict__ src, const float* __restrict__ ea,
                            const float* __restrict__ aS, const float* __restrict__ aD,
                            const float* __restrict__ x, const float* __restrict__ ced,
                            float* __restrict__ agg, int N)
{
    int w = (blockIdx.x * blockDim.x + threadIdx.x) >> 5;
    int lane = threadIdx.x & 31;
    if (w >= N) return;
    int beg = off[w], end = off[w + 1];
    float c0 = ced[0], c1 = ced[1];
    float ad = aD[w];

    float m = -3.0e38f;
    for (int i = beg + lane; i < end; i += 32) {
        int e = eid[i];
        float lg = aS[src[e]] + ad + c0 * ea[2 * e] + c1 * ea[2 * e + 1];
        lg = lg > 0.f ? lg : 0.2f * lg;
        m = fmaxf(m, lg);
    }
#pragma unroll
    for (int o = 16; o > 0; o >>= 1) m = fmaxf(m, __shfl_xor_sync(0xffffffffu, m, o));

    float den = 0.f;
    for (int i = beg + lane; i < end; i += 32) {
        int e = eid[i];
        float lg = aS[src[e]] + ad + c0 * ea[2 * e] + c1 * ea[2 * e + 1];
        lg = lg > 0.f ? lg : 0.2f * lg;
        den += expf(lg - m);
    }
#pragma unroll
    for (int o = 16; o > 0; o >>= 1) den += __shfl_xor_sync(0xffffffffu, den, o);

    float inv = (den > 0.f) ? 1.f / den : 0.f;
    float acc[8] = {0.f, 0.f, 0.f, 0.f, 0.f, 0.f, 0.f, 0.f};
    for (int i = beg; i < end; i++) {
        int e = eid[i];
        int s = src[e];
        float lg = aS[s] + ad + c0 * ea[2 * e] + c1 * ea[2 * e + 1];
        lg = lg > 0.f ? lg : 0.2f * lg;
        float wt = expf(lg - m) * inv;
        const float* xr = x + (long)s * kD;
#pragma unroll
        for (int k = 0; k < 8; k++) acc[k] += wt * xr[lane + 32 * k];
    }
    float* ar = agg + (long)w * kD;
#pragma unroll
    for (int k = 0; k < 8; k++) ar[lane + 32 * k] = acc[k];
}

// ---------------- GEMM: out = relu(A@W + bias) (+ prev)   A:[M,256] W:[256,256] ----------------
__global__ void k_gemm(const float* __restrict__ A, const float* __restrict__ W,
                       const float* __restrict__ bias, const float* __restrict__ prev,
                       float* __restrict__ out, int M)
{
    __shared__ float As[16][64];
    __shared__ float Bs[16][64];
    int tid = threadIdx.x;
    int tx = tid & 15, ty = tid >> 4;
    int rowBase = blockIdx.y * 64, colBase = blockIdx.x * 64;
    float acc[4][4] = {};

    for (int k0 = 0; k0 < kD; k0 += 16) {
#pragma unroll
        for (int i = tid; i < 64 * 16; i += 256) {
            int mm = i >> 4, kk = i & 15;
            int gm = rowBase + mm;
            As[kk][mm] = (gm < M) ? A[(long)gm * kD + k0 + kk] : 0.f;
        }
#pragma unroll
        for (int i = tid; i < 16 * 64; i += 256) {
            int kk = i >> 6, nn = i & 63;
            Bs[kk][nn] = W[(long)(k0 + kk) * kD + colBase + nn];
        }
        __syncthreads();
#pragma unroll
        for (int kk = 0; kk < 16; kk++) {
            float4 a4 = *reinterpret_cast<const float4*>(&As[kk][ty * 4]);
            float4 b4 = *reinterpret_cast<const float4*>(&Bs[kk][tx * 4]);
            float av[4] = {a4.x, a4.y, a4.z, a4.w};
            float bv[4] = {b4.x, b4.y, b4.z, b4.w};
#pragma unroll
            for (int i = 0; i < 4; i++)
#pragma unroll
                for (int j = 0; j < 4; j++) acc[i][j] += av[i] * bv[j];
        }
        __syncthreads();
    }

#pragma unroll
    for (int i = 0; i < 4; i++) {
        int gm = rowBase + ty * 4 + i;
        if (gm >= M) continue;
#pragma unroll
        for (int j = 0; j < 4; j++) {
            int gn = colBase + tx * 4 + j;
            float v = acc[i][j] + bias[gn];
            v = fmaxf(v, 0.f);
            if (prev) v += prev[(long)gm * kD + gn];
            out[(long)gm * kD + gn] = v;
        }
    }
}

// ---------------- pooling ----------------
__global__ void k_pool_nodes(const float* __restrict__ x, const int* __restrict__ batch,
                             float* __restrict__ sum, float* __restrict__ cnt, int N)
{
    long idx = (long)blockIdx.x * blockDim.x + threadIdx.x;
    if (idx >= (long)N * kD) return;
    int n = (int)(idx >> 8);
    int d = (int)(idx & 255);
    int b = batch[n];
    atomicAdd(&sum[b * kD + d], x[idx]);
    if (d == 0) atomicAdd(&cnt[b], 1.f);
}

__global__ void k_pool_edges(const float* __restrict__ ea, const int* __restrict__ src,
                             const int* __restrict__ hbatch,
                             const float* __restrict__ Wm, const float* __restrict__ bm,
                             float* __restrict__ esum, float* __restrict__ ecnt)
{
    int e = blockIdx.x * blockDim.x + threadIdx.x;
    if (e >= kE) return;
    float e0 = ea[2 * e], e1 = ea[2 * e + 1];
    int b = hbatch[src[e]];
    atomicAdd(&ecnt[b], 1.f);
#pragma unroll
    for (int j = 0; j < 32; j++) {
        float v = fmaxf(e0 * Wm[j] + e1 * Wm[32 + j] + bm[j], 0.f);
        atomicAdd(&esum[b * 32 + j], v);
    }
}

// ---------------- final: graph emb -> 2 softmax heads ----------------
__global__ void k_final(const float* __restrict__ hsum, const float* __restrict__ hcnt,
                        const float* __restrict__ osum, const float* __restrict__ ocnt,
                        const float* __restrict__ esum, const float* __restrict__ ecnt,
                        const float* __restrict__ Wp1, const float* __restrict__ bp1,
                        const float* __restrict__ Wp2, const float* __restrict__ bp2,
                        float* __restrict__ out)
{
    __shared__ float emb[2 * kD + 32];
    __shared__ float red[128];
    int b = blockIdx.x, t = threadIdx.x;
    float hc = fmaxf(hcnt[b], 1.f), oc = fmaxf(ocnt[b], 1.f), ec = fmaxf(ecnt[b], 1.f);
    for (int k = t; k < kD; k += 128) {
        emb[k]      = hsum[b * kD + k] / hc;
        emb[kD + k] = osum[b * kD + k] / oc;
    }
    for (int k = t; k < 32; k += 128) emb[2 * kD + k] = esum[b * 32 + k] / ec;
    __syncthreads();

    for (int head = 0; head < 2; head++) {
        const float* W  = head ? Wp2 : Wp1;
        const float* bb = head ? bp2 : bp1;
        float v = -3.0e38f;
        if (t < kC) {
            v = bb[t];
            for (int k = 0; k < 2 * kD + 32; k++) v += emb[k] * W[k * kC + t];
        }
        red[t] = v;
        __syncthreads();
        for (int s = 64; s > 0; s >>= 1) {
            if (t < s) red[t] = fmaxf(red[t], red[t + s]);
            __syncthreads();
        }
        float mx = red[0];
        __syncthreads();
        float ex = (t < kC) ? expf(v - mx) : 0.f;
        red[t] = ex;
        __syncthreads();
        for (int s = 64; s > 0; s >>= 1) {
            if (t < s) red[t] += red[t + s];
            __syncthreads();
        }
        float sm = red[0];
        __syncthreads();
        if (t < kC) out[(b * 2 + head) * kC + t] = ex / sm;
    }
}

// ---------------- launch ----------------
extern "C" void kernel_launch(void* const* d_in, const int* in_sizes, int n_in,
                              void* d_out, int out_size)
{
    const float* x_human = (const float*)d_in[0];
    const float* x_object = (const float*)d_in[1];
    const int* ei_ho = (const int*)d_in[2];
    const int* ei_oh = (const int*)d_in[3];
    const float* ea_ho = (const float*)d_in[4];
    const float* ea_oh = (const float*)d_in[5];
    const int* hbatch = (const int*)d_in[6];
    const int* obatch = (const int*)d_in[7];
    const float* Wsrc_ho = (const float*)d_in[8];
    const float* Wdst_ho = (const float*)d_in[9];
    const float* asrc_ho = (const float*)d_in[10];
    const float* adst_ho = (const float*)d_in[11];
    const float* Wedge_ho = (const float*)d_in[12];
    const float* aedge_ho = (const float*)d_in[13];
    const float* bias_ho = (const float*)d_in[14];
    const float* Wsrc_oh = (const float*)d_in[15];
    const float* Wdst_oh = (const float*)d_in[16];
    const float* asrc_oh = (const float*)d_in[17];
    const float* adst_oh = (const float*)d_in[18];
    const float* Wedge_oh = (const float*)d_in[19];
    const float* aedge_oh = (const float*)d_in[20];
    const float* bias_oh = (const float*)d_in[21];
    const float* W_emlp = (const float*)d_in[22];
    const float* b_emlp = (const float*)d_in[23];
    const float* W_p1 = (const float*)d_in[24];
    const float* b_p1 = (const float*)d_in[25];
    const float* W_p2 = (const float*)d_in[26];
    const float* b_p2 = (const float*)d_in[27];

    float *h0, *h1, *o0, *o1, *agg;
    float *aSho, *aDoh, *aDho, *aSoh, *vsrc, *vdst, *ced;
    float *hsum, *osum, *esum, *hcnt, *ocnt, *ecnt;
    int *off, *eid, *cur;
    cudaGetSymbolAddress((void**)&h0, g_h0);
    cudaGetSymbolAddress((void**)&h1, g_h1);
    cudaGetSymbolAddress((void**)&o0, g_o0);
    cudaGetSymbolAddress((void**)&o1, g_o1);
    cudaGetSymbolAddress((void**)&agg, g_agg);
    cudaGetSymbolAddress((void**)&aSho, g_aSho);
    cudaGetSymbolAddress((void**)&aDoh, g_aDoh);
    cudaGetSymbolAddress((void**)&aDho, g_aDho);
    cudaGetSymbolAddress((void**)&aSoh, g_aSoh);
    cudaGetSymbolAddress((void**)&vsrc, g_vsrc);
    cudaGetSymbolAddress((void**)&vdst, g_vdst);
    cudaGetSymbolAddress((void**)&ced, g_cedge);
    cudaGetSymbolAddress((void**)&off, g_off);
    cudaGetSymbolAddress((void**)&eid, g_eid);
    cudaGetSymbolAddress((void**)&cur, g_cursor);
    cudaGetSymbolAddress((void**)&hsum, g_hsum);
    cudaGetSymbolAddress((void**)&osum, g_osum);
    cudaGetSymbolAddress((void**)&esum, g_esum);
    cudaGetSymbolAddress((void**)&hcnt, g_hcnt);
    cudaGetSymbolAddress((void**)&ocnt, g_ocnt);
    cudaGetSymbolAddress((void**)&ecnt, g_ecnt);

    const int EB = (kE + 255) / 256;

    // ---- CSR build for both relations (dst = second row of edge_index) ----
    cudaMemsetAsync(cur, 0, sizeof(int) * 2 * kNH);
    k_hist<<<EB, 256>>>(ei_ho + kE, cur);
    k_hist<<<EB, 256>>>(ei_oh + kE, cur + kNH);
    k_scan<<<1, 1024>>>(cur, off, kNO, kE);
    k_scan<<<1, 1024>>>(cur + kNH, off + (kNH + 1), kNH, kE);
    k_scatter<<<EB, 256>>>(ei_ho + kE, cur, eid);
    k_scatter<<<EB, 256>>>(ei_oh + kE, cur + kNH, eid + kE);

    // ---- tiny per-layer attention-vector precompute ----
    k_precompute<<<2 * kL, 256>>>(Wsrc_ho, asrc_ho, Wdst_ho, adst_ho, Wedge_ho, aedge_ho,
                                  Wsrc_oh, asrc_oh, Wdst_oh, adst_oh, Wedge_oh, aedge_oh);

    // ---- 8 layers ----
    const float* cur_h = x_human;
    const float* cur_o = x_object;
    for (int l = 0; l < kL; l++) {
        float* nh = (l & 1) ? h1 : h0;
        float* no = (l & 1) ? o1 : o0;

        k_matvec2<<<kNH / 8, 256>>>(cur_h, vsrc + (0 * kL + l) * kD,
                                    vdst + (1 * kL + l) * kD, aSho, aDoh, kNH);
        k_matvec2<<<kNO / 8, 256>>>(cur_o, vdst + (0 * kL + l) * kD,
                                    vsrc + (1 * kL + l) * kD, aDho, aSoh, kNO);

        // GAT ho: humans -> objects
        k_aggregate<<<kNO / 8, 256>>>(off, eid, ei_ho, ea_ho, aSho, aDho,
                                      cur_h, ced + (0 * kL + l) * 2, agg, kNO);
        k_gemm<<<dim3(4, (kNO + 63) / 64), 256>>>(agg, Wsrc_ho + (long)l * kD * kD,
                                                  bias_ho + l * kD,
                                                  l ? cur_o : nullptr, no, kNO);
        // GAT oh: objects -> humans
        k_aggregate<<<kNH / 8, 256>>>(off + (kNH + 1), eid + kE, ei_oh, ea_oh, aSoh, aDoh,
                                      cur_o, ced + (1 * kL + l) * 2, agg, kNH);
        k_gemm<<<dim3(4, (kNH + 63) / 64), 256>>>(agg, Wsrc_oh + (long)l * kD * kD,
                                                  bias_oh + l * kD,
                                                  l ? cur_h : nullptr, nh, kNH);
        cur_h = nh;
        cur_o = no;
    }

    // ---- pooling ----
    cudaMemsetAsync(hsum, 0, sizeof(float) * kB * kD);
    cudaMemsetAsync(osum, 0, sizeof(float) * kB * kD);
    cudaMemsetAsync(esum, 0, sizeof(float) * kB * 32);
    cudaMemsetAsync(hcnt, 0, sizeof(float) * kB);
    cudaMemsetAsync(ocnt, 0, sizeof(float) * kB);
    cudaMemsetAsync(ecnt, 0, sizeof(float) * kB);
    k_pool_nodes<<<kNH, 256>>>(cur_h, hbatch, hsum, hcnt, kNH);
    k_pool_nodes<<<kNO, 256>>>(cur_o, obatch, osum, ocnt, kNO);
    k_pool_edges<<<EB, 256>>>(ea_ho, ei_ho, hbatch, W_emlp, b_emlp, esum, ecnt);

    // ---- classifier heads ----
    k_final<<<kB, 128>>>(hsum, hcnt, osum, ocnt, esum, ecnt,
                         W_p1, b_p1, W_p2, b_p2, (float*)d_out);
}

// round 4
// speedup vs baseline: 1.6062x; 1.6062x over previous
#include <cuda_runtime.h>
#include <cstdint>

static constexpr int kNH = 50000;
static constexpr int kNO = 50000;
static constexpr int kE  = 500000;
static constexpr int kD  = 256;
static constexpr int kL  = 8;
static constexpr int kB  = 512;
static constexpr int kC  = 117;

// ---------------- device scratch (static, no runtime alloc) ----------------
__device__ float g_h0[kNH * kD];
__device__ float g_h1[kNH * kD];
__device__ float g_o0[kNO * kD];
__device__ float g_o1[kNO * kD];
__device__ float g_agg[kNH * kD];

__device__ float g_aSho[kNH], g_aDoh[kNH], g_aDho[kNO], g_aSoh[kNO];

__device__ float g_vsrc[2 * kL * kD];
__device__ float g_vdst[2 * kL * kD];
__device__ float g_cedge[2 * kL * 2];

// W^T, split hi/lo tf32: [rel*8+layer][hi/lo][n=256][k=256]
__device__ float g_wT[2 * kL * 2 * kD * kD];

__device__ int g_off[2 * (kNH + 1)];
__device__ int g_eid[2 * kE];
__device__ int g_cursor[2 * kNH];

__device__ float g_hsum[kB * kD], g_osum[kB * kD], g_esum[kB * 32];
__device__ float g_hcnt[kB], g_ocnt[kB], g_ecnt[kB];

__device__ __forceinline__ float tf32_rna(float x) {
    uint32_t r;
    asm("cvt.rna.tf32.f32 %0, %1;" : "=r"(r) : "f"(x));
    return __uint_as_float(r);
}

// ============================================================================
// small precompute: vsrc = Wsrc@asrc, vdst = Wdst@adst, cedge = Wedge@aedge
// ============================================================================
__global__ void k_precompute(
    const float* __restrict__ Wsrc0, const float* __restrict__ asrc0,
    const float* __restrict__ Wdst0, const float* __restrict__ adst0,
    const float* __restrict__ Wedge0, const float* __restrict__ aedge0,
    const float* __restrict__ Wsrc1, const float* __restrict__ asrc1,
    const float* __restrict__ Wdst1, const float* __restrict__ adst1,
    const float* __restrict__ Wedge1, const float* __restrict__ aedge1)
{
    int rel = blockIdx.x / kL;
    int l   = blockIdx.x % kL;
    const float* Wsrc  = rel ? Wsrc1  : Wsrc0;
    const float* asrc  = rel ? asrc1  : asrc0;
    const float* Wdst  = rel ? Wdst1  : Wdst0;
    const float* adst  = rel ? adst1  : adst0;
    const float* Wedge = rel ? Wedge1 : Wedge0;
    const float* aedge = rel ? aedge1 : aedge0;

    int i = threadIdx.x;
    float s1 = 0.f, s2 = 0.f;
    const float* wsr = Wsrc + (long)l * kD * kD + (long)i * kD;
    const float* wdr = Wdst + (long)l * kD * kD + (long)i * kD;
    const float* as  = asrc + l * kD;
    const float* ad  = adst + l * kD;
    for (int j = 0; j < kD; j++) { s1 += wsr[j] * as[j]; s2 += wdr[j] * ad[j]; }
    g_vsrc[(rel * kL + l) * kD + i] = s1;
    g_vdst[(rel * kL + l) * kD + i] = s2;
    if (i < 2) {
        float c = 0.f;
        const float* we = Wedge + (long)l * 2 * kD + (long)i * kD;
        const float* ae = aedge + l * kD;
        for (int j = 0; j < kD; j++) c += we[j] * ae[j];
        g_cedge[(rel * kL + l) * 2 + i] = c;
    }
}

// ---------------- transpose + tf32 hi/lo split of Wsrc weights ----------------
__global__ void k_wprep(const float* __restrict__ W_ho, const float* __restrict__ W_oh)
{
    int rl = blockIdx.x;                 // 0..15 = rel*8 + layer
    int rel = rl >> 3;
    const float* W = (rel ? W_oh : W_ho) + (long)(rl & 7) * kD * kD;
    int tile = blockIdx.y;               // 0..63
    int tk = (tile & 7) * 32, tn = (tile >> 3) * 32;
    __shared__ float sh[32][33], sl[32][33];
    int tx = threadIdx.x, ty = threadIdx.y;
    for (int yy = ty; yy < 32; yy += 8) {
        float v = W[(long)(tk + yy) * kD + tn + tx];
        float h = tf32_rna(v);
        sh[yy][tx] = h;
        sl[yy][tx] = tf32_rna(v - h);
    }
    __syncthreads();
    float* outHi = g_wT + (long)(rl * 2 + 0) * kD * kD;
    float* outLo = g_wT + (long)(rl * 2 + 1) * kD * kD;
    for (int yy = ty; yy < 32; yy += 8) {
        outHi[(long)(tn + yy) * kD + tk + tx] = sh[tx][yy];
        outLo[(long)(tn + yy) * kD + tk + tx] = sl[tx][yy];
    }
}

// ---------------- CSR build ----------------
__global__ void k_hist(const int* __restrict__ dst, int* __restrict__ cnt)
{
    int e = blockIdx.x * blockDim.x + threadIdx.x;
    if (e < kE) atomicAdd(&cnt[dst[e]], 1);
}

__global__ void k_scan(int* __restrict__ cnt, int* __restrict__ off, int N, int total)
{
    __shared__ int warpsums[32];
    __shared__ int s_carry;
    int t = threadIdx.x, lane = t & 31, wid = t >> 5;
    if (t == 0) s_carry = 0;
    __syncthreads();
    for (int base = 0; base < N; base += 1024) {
        int i = base + t;
        int c = (i < N) ? cnt[i] : 0;
        int v = c;
#pragma unroll
        for (int o = 1; o < 32; o <<= 1) {
            int u = __shfl_up_sync(0xffffffffu, v, o);
            if (lane >= o) v += u;
        }
        if (lane == 31) warpsums[wid] = v;
        __syncthreads();
        if (wid == 0) {
            int w = warpsums[lane];
#pragma unroll
            for (int o = 1; o < 32; o <<= 1) {
                int u = __shfl_up_sync(0xffffffffu, w, o);
                if (lane >= o) w += u;
            }
            warpsums[lane] = w;
        }
        __syncthreads();
        int excl = v - c + (wid ? warpsums[wid - 1] : 0) + s_carry;
        if (i < N) { off[i] = excl; cnt[i] = excl; }
        __syncthreads();
        if (t == 1023) s_carry += v + warpsums[30];
        __syncthreads();
    }
    if (t == 0) off[N] = total;
}

__global__ void k_scatter(const int* __restrict__ dst, int* __restrict__ cur,
                          int* __restrict__ eid)
{
    int e = blockIdx.x * blockDim.x + threadIdx.x;
    if (e >= kE) return;
    int p = atomicAdd(&cur[dst[e]], 1);
    eid[p] = e;
}

// ---------------- fused dual matvec ----------------
__global__ void k_matvec2(const float* __restrict__ x,
                          const float* __restrict__ v1, const float* __restrict__ v2,
                          float* __restrict__ a1, float* __restrict__ a2, int N)
{
    int w = (blockIdx.x * blockDim.x + threadIdx.x) >> 5;
    int lane = threadIdx.x & 31;
    if (w >= N) return;
    const float* xr = x + (long)w * kD;
    float s1 = 0.f, s2 = 0.f;
#pragma unroll
    for (int k = 0; k < 8; k++) {
        float xv = xr[lane + 32 * k];
        s1 += xv * v1[lane + 32 * k];
        s2 += xv * v2[lane + 32 * k];
    }
#pragma unroll
    for (int o = 16; o > 0; o >>= 1) {
        s1 += __shfl_xor_sync(0xffffffffu, s1, o);
        s2 += __shfl_xor_sync(0xffffffffu, s2, o);
    }
    if (lane == 0) { a1[w] = s1; a2[w] = s2; }
}

// ---------------- per-dst segment softmax + weighted gather-aggregate ----------------
__global__ void k_aggregate(const int* __restrict__ off, const int* __restrict__ eid,
                            const int* __restrict__ src, const float* __restrict__ ea,
                            const float* __restrict__ aS, const float* __restrict__ aD,
                            const float* __restrict__ x, const float* __restrict__ ced,
                            float* __restrict__ agg, int N)
{
    int w = (blockIdx.x * blockDim.x + threadIdx.x) >> 5;
    int lane = threadIdx.x & 31;
    if (w >= N) return;
    int beg = off[w], end = off[w + 1];
    float c0 = ced[0], c1 = ced[1];
    float ad = aD[w];

    float m = -3.0e38f;
    for (int i = beg + lane; i < end; i += 32) {
        int e = eid[i];
        float lg = aS[src[e]] + ad + c0 * ea[2 * e] + c1 * ea[2 * e + 1];
        lg = lg > 0.f ? lg : 0.2f * lg;
        m = fmaxf(m, lg);
    }
#pragma unroll
    for (int o = 16; o > 0; o >>= 1) m = fmaxf(m, __shfl_xor_sync(0xffffffffu, m, o));

    float den = 0.f;
    for (int i = beg + lane; i < end; i += 32) {
        int e = eid[i];
        float lg = aS[src[e]] + ad + c0 * ea[2 * e] + c1 * ea[2 * e + 1];
        lg = lg > 0.f ? lg : 0.2f * lg;
        den += expf(lg - m);
    }
#pragma unroll
    for (int o = 16; o > 0; o >>= 1) den += __shfl_xor_sync(0xffffffffu, den, o);

    float inv = (den > 0.f) ? 1.f / den : 0.f;
    float acc[8] = {0.f, 0.f, 0.f, 0.f, 0.f, 0.f, 0.f, 0.f};
    for (int i = beg; i < end; i++) {
        int e = eid[i];
        int s = src[e];
        float lg = aS[s] + ad + c0 * ea[2 * e] + c1 * ea[2 * e + 1];
        lg = lg > 0.f ? lg : 0.2f * lg;
        float wt = expf(lg - m) * inv;
        const float* xr = x + (long)s * kD;
#pragma unroll
        for (int k = 0; k < 8; k++) acc[k] += wt * xr[lane + 32 * k];
    }
    float* ar = agg + (long)w * kD;
#pragma unroll
    for (int k = 0; k < 8; k++) ar[lane + 32 * k] = acc[k];
}

// ============================================================================
// mma.sync tf32 GEMM (3xTF32): out = relu(A@W + bias) (+ prev)
// A:[M,256] fp32, WT: hi/lo [256n][256k]. CTA tile 128M x 128N, 16 warps (32x32 each)
// ============================================================================
static constexpr int SASTRIDE = 36;  // 32 + 4 pad: (4m+k)&31 unique -> conflict-free frags
static constexpr int GEMM_SMEM = 4 * 128 * SASTRIDE * 4;  // aHi,aLo,bHi,bLo = 73728 B

__device__ __forceinline__ void mma_tf32(float* c, const uint32_t* a, const uint32_t* b) {
    asm volatile(
        "mma.sync.aligned.m16n8k8.row.col.f32.tf32.tf32.f32 "
        "{%0,%1,%2,%3}, {%4,%5,%6,%7}, {%8,%9}, {%0,%1,%2,%3};\n"
        : "+f"(c[0]), "+f"(c[1]), "+f"(c[2]), "+f"(c[3])
        : "r"(a[0]), "r"(a[1]), "r"(a[2]), "r"(a[3]), "r"(b[0]), "r"(b[1]));
}

__global__ void __launch_bounds__(512) k_gemm_mma(
    const float* __restrict__ A, const float* __restrict__ WT,
    const float* __restrict__ bias, const float* __restrict__ prev,
    float* __restrict__ out, int M)
{
    extern __shared__ float smem[];
    float* sAhi = smem;
    float* sAlo = smem + 128 * SASTRIDE;
    float* sBhi = smem + 2 * 128 * SASTRIDE;
    float* sBlo = smem + 3 * 128 * SASTRIDE;

    const int tid = threadIdx.x;
    const int w = tid >> 5, lane = tid & 31;
    const int wm = w & 3, wn = w >> 2;       // 4x4 warp grid, each warp 32m x 32n
    const int grp = lane >> 2, qt = lane & 3;
    const int mBase = blockIdx.y * 128;
    const int nBase = blockIdx.x * 128;

    const float* WThi = WT + (long)nBase * kD;
    const float* WTlo = WT + 65536 + (long)nBase * kD;

    float acc[2][4][4];
#pragma unroll
    for (int i = 0; i < 2; i++)
#pragma unroll
        for (int j = 0; j < 4; j++)
#pragma unroll
            for (int q = 0; q < 4; q++) acc[i][j][q] = 0.f;

    for (int c = 0; c < 8; c++) {
        // load A chunk 128x32, split hi/lo
#pragma unroll
        for (int it = 0; it < 2; it++) {
            int idx = tid + it * 512;            // 0..1023 float4s
            int r = idx >> 3, q = idx & 7;
            int gm = mBase + r;
            float4 v = (gm < M) ? *(const float4*)&A[(long)gm * kD + c * 32 + q * 4]
                                : make_float4(0.f, 0.f, 0.f, 0.f);
            float4 h, l;
            h.x = tf32_rna(v.x); l.x = tf32_rna(v.x - h.x);
            h.y = tf32_rna(v.y); l.y = tf32_rna(v.y - h.y);
            h.z = tf32_rna(v.z); l.z = tf32_rna(v.z - h.z);
            h.w = tf32_rna(v.w); l.w = tf32_rna(v.w - h.w);
            *(float4*)&sAhi[r * SASTRIDE + q * 4] = h;
            *(float4*)&sAlo[r * SASTRIDE + q * 4] = l;
        }
        // load B chunk 128x32 (pre-split)
#pragma unroll
        for (int it = 0; it < 2; it++) {
            int idx = tid + it * 512;
            int n = idx >> 3, q = idx & 7;
            *(float4*)&sBhi[n * SASTRIDE + q * 4] =
                *(const float4*)&WThi[(long)n * kD + c * 32 + q * 4];
            *(float4*)&sBlo[n * SASTRIDE + q * 4] =
                *(const float4*)&WTlo[(long)n * kD + c * 32 + q * 4];
        }
        __syncthreads();

        const uint32_t* uAhi = (const uint32_t*)sAhi;
        const uint32_t* uAlo = (const uint32_t*)sAlo;
        const uint32_t* uBhi = (const uint32_t*)sBhi;
        const uint32_t* uBlo = (const uint32_t*)sBlo;
#pragma unroll
        for (int ks = 0; ks < 4; ks++) {
            int kb = ks * 8;
            uint32_t ahi[2][4], alo[2][4], bhi[4][2], blo[4][2];
#pragma unroll
            for (int i = 0; i < 2; i++) {
                int r0 = (wm * 32 + i * 16 + grp) * SASTRIDE + kb + qt;
                int r1 = r0 + 8 * SASTRIDE;
                ahi[i][0] = uAhi[r0];     ahi[i][1] = uAhi[r1];
                ahi[i][2] = uAhi[r0 + 4]; ahi[i][3] = uAhi[r1 + 4];
                alo[i][0] = uAlo[r0];     alo[i][1] = uAlo[r1];
                alo[i][2] = uAlo[r0 + 4]; alo[i][3] = uAlo[r1 + 4];
            }
#pragma unroll
            for (int j = 0; j < 4; j++) {
                int c0 = (wn * 32 + j * 8 + grp) * SASTRIDE + kb + qt;
                bhi[j][0] = uBhi[c0]; bhi[j][1] = uBhi[c0 + 4];
                blo[j][0] = uBlo[c0]; blo[j][1] = uBlo[c0 + 4];
            }
#pragma unroll
            for (int i = 0; i < 2; i++)
#pragma unroll
                for (int j = 0; j < 4; j++) {
                    mma_tf32(acc[i][j], ahi[i], bhi[j]);
                    mma_tf32(acc[i][j], ahi[i], blo[j]);
                    mma_tf32(acc[i][j], alo[i], bhi[j]);
                }
        }
        __syncthreads();
    }

    // epilogue
#pragma unroll
    for (int i = 0; i < 2; i++) {
#pragma unroll
        for (int h = 0; h < 2; h++) {
            int row = mBase + wm * 32 + i * 16 + grp + h * 8;
            if (row >= M) continue;
#pragma unroll
            for (int j = 0; j < 4; j++) {
                int col = nBase + wn * 32 + j * 8 + qt * 2;
                float v0 = acc[i][j][h * 2 + 0] + bias[col];
                float v1 = acc[i][j][h * 2 + 1] + bias[col + 1];
                v0 = fmaxf(v0, 0.f);
                v1 = fmaxf(v1, 0.f);
                if (prev) {
                    float2 pv = *(const float2*)&prev[(long)row * kD + col];
                    v0 += pv.x; v1 += pv.y;
                }
                float2 o; o.x = v0; o.y = v1;
                *(float2*)&out[(long)row * kD + col] = o;
            }
        }
    }
}

// ---------------- pooling ----------------
__global__ void k_pool_nodes(const float* __restrict__ x, const int* __restrict__ batch,
                             float* __restrict__ sum, float* __restrict__ cnt, int N)
{
    long idx = (long)blockIdx.x * blockDim.x + threadIdx.x;
    if (idx >= (long)N * kD) return;
    int n = (int)(idx >> 8);
    int d = (int)(idx & 255);
    int b = batch[n];
    atomicAdd(&sum[b * kD + d], x[idx]);
    if (d == 0) atomicAdd(&cnt[b], 1.f);
}

__global__ void k_pool_edges(const float* __restrict__ ea, const int* __restrict__ src,
                             const int* __restrict__ hbatch,
                             const float* __restrict__ Wm, const float* __restrict__ bm,
                             float* __restrict__ esum, float* __restrict__ ecnt)
{
    int e = blockIdx.x * blockDim.x + threadIdx.x;
    if (e >= kE) return;
    float e0 = ea[2 * e], e1 = ea[2 * e + 1];
    int b = hbatch[src[e]];
    atomicAdd(&ecnt[b], 1.f);
#pragma unroll
    for (int j = 0; j < 32; j++) {
        float v = fmaxf(e0 * Wm[j] + e1 * Wm[32 + j] + bm[j], 0.f);
        atomicAdd(&esum[b * 32 + j], v);
    }
}

// ---------------- final: graph emb -> 2 softmax heads ----------------
__global__ void k_final(const float* __restrict__ hsum, const float* __restrict__ hcnt,
                        const float* __restrict__ osum, const float* __restrict__ ocnt,
                        const float* __restrict__ esum, const float* __restrict__ ecnt,
                        const float* __restrict__ Wp1, const float* __restrict__ bp1,
                        const float* __restrict__ Wp2, const float* __restrict__ bp2,
                        float* __restrict__ out)
{
    __shared__ float emb[2 * kD + 32];
    __shared__ float red[128];
    int b = blockIdx.x, t = threadIdx.x;
    float hc = fmaxf(hcnt[b], 1.f), oc = fmaxf(ocnt[b], 1.f), ec = fmaxf(ecnt[b], 1.f);
    for (int k = t; k < kD; k += 128) {
        emb[k]      = hsum[b * kD + k] / hc;
        emb[kD + k] = osum[b * kD + k] / oc;
    }
    for (int k = t; k < 32; k += 128) emb[2 * kD + k] = esum[b * 32 + k] / ec;
    __syncthreads();

    for (int head = 0; head < 2; head++) {
        const float* W  = head ? Wp2 : Wp1;
        const float* bb = head ? bp2 : bp1;
        float v = -3.0e38f;
        if (t < kC) {
            v = bb[t];
            for (int k = 0; k < 2 * kD + 32; k++) v += emb[k] * W[k * kC + t];
        }
        red[t] = v;
        __syncthreads();
        for (int s = 64; s > 0; s >>= 1) {
            if (t < s) red[t] = fmaxf(red[t], red[t + s]);
            __syncthreads();
        }
        float mx = red[0];
        __syncthreads();
        float ex = (t < kC) ? expf(v - mx) : 0.f;
        red[t] = ex;
        __syncthreads();
        for (int s = 64; s > 0; s >>= 1) {
            if (t < s) red[t] += red[t + s];
            __syncthreads();
        }
        float sm = red[0];
        __syncthreads();
        if (t < kC) out[(b * 2 + head) * kC + t] = ex / sm;
    }
}

// ---------------- launch ----------------
extern "C" void kernel_launch(void* const* d_in, const int* in_sizes, int n_in,
                              void* d_out, int out_size)
{
    const float* x_human = (const float*)d_in[0];
    const float* x_object = (const float*)d_in[1];
    const int* ei_ho = (const int*)d_in[2];
    const int* ei_oh = (const int*)d_in[3];
    const float* ea_ho = (const float*)d_in[4];
    const float* ea_oh = (const float*)d_in[5];
    const int* hbatch = (const int*)d_in[6];
    const int* obatch = (const int*)d_in[7];
    const float* Wsrc_ho = (const float*)d_in[8];
    const float* Wdst_ho = (const float*)d_in[9];
    const float* asrc_ho = (const float*)d_in[10];
    const float* adst_ho = (const float*)d_in[11];
    const float* Wedge_ho = (const float*)d_in[12];
    const float* aedge_ho = (const float*)d_in[13];
    const float* bias_ho = (const float*)d_in[14];
    const float* Wsrc_oh = (const float*)d_in[15];
    const float* Wdst_oh = (const float*)d_in[16];
    const float* asrc_oh = (const float*)d_in[17];
    const float* adst_oh = (const float*)d_in[18];
    const float* Wedge_oh = (const float*)d_in[19];
    const float* aedge_oh = (const float*)d_in[20];
    const float* bias_oh = (const float*)d_in[21];
    const float* W_emlp = (const float*)d_in[22];
    const float* b_emlp = (const float*)d_in[23];
    const float* W_p1 = (const float*)d_in[24];
    const float* b_p1 = (const float*)d_in[25];
    const float* W_p2 = (const float*)d_in[26];
    const float* b_p2 = (const float*)d_in[27];

    float *h0, *h1, *o0, *o1, *agg;
    float *aSho, *aDoh, *aDho, *aSoh, *vsrc, *vdst, *ced, *wT;
    float *hsum, *osum, *esum, *hcnt, *ocnt, *ecnt;
    int *off, *eid, *cur;
    cudaGetSymbolAddress((void**)&h0, g_h0);
    cudaGetSymbolAddress((void**)&h1, g_h1);
    cudaGetSymbolAddress((void**)&o0, g_o0);
    cudaGetSymbolAddress((void**)&o1, g_o1);
    cudaGetSymbolAddress((void**)&agg, g_agg);
    cudaGetSymbolAddress((void**)&aSho, g_aSho);
    cudaGetSymbolAddress((void**)&aDoh, g_aDoh);
    cudaGetSymbolAddress((void**)&aDho, g_aDho);
    cudaGetSymbolAddress((void**)&aSoh, g_aSoh);
    cudaGetSymbolAddress((void**)&vsrc, g_vsrc);
    cudaGetSymbolAddress((void**)&vdst, g_vdst);
    cudaGetSymbolAddress((void**)&ced, g_cedge);
    cudaGetSymbolAddress((void**)&wT, g_wT);
    cudaGetSymbolAddress((void**)&off, g_off);
    cudaGetSymbolAddress((void**)&eid, g_eid);
    cudaGetSymbolAddress((void**)&cur, g_cursor);
    cudaGetSymbolAddress((void**)&hsum, g_hsum);
    cudaGetSymbolAddress((void**)&osum, g_osum);
    cudaGetSymbolAddress((void**)&esum, g_esum);
    cudaGetSymbolAddress((void**)&hcnt, g_hcnt);
    cudaGetSymbolAddress((void**)&ocnt, g_ocnt);
    cudaGetSymbolAddress((void**)&ecnt, g_ecnt);

    cudaFuncSetAttribute(k_gemm_mma, cudaFuncAttributeMaxDynamicSharedMemorySize, GEMM_SMEM);

    const int EB = (kE + 255) / 256;
    const dim3 GEMM_GRID(2, (kNH + 127) / 128);  // N split x M tiles

    // ---- CSR build for both relations ----
    cudaMemsetAsync(cur, 0, sizeof(int) * 2 * kNH);
    k_hist<<<EB, 256>>>(ei_ho + kE, cur);
    k_hist<<<EB, 256>>>(ei_oh + kE, cur + kNH);
    k_scan<<<1, 1024>>>(cur, off, kNO, kE);
    k_scan<<<1, 1024>>>(cur + kNH, off + (kNH + 1), kNH, kE);
    k_scatter<<<EB, 256>>>(ei_ho + kE, cur, eid);
    k_scatter<<<EB, 256>>>(ei_oh + kE, cur + kNH, eid + kE);

    // ---- per-layer precompute ----
    k_precompute<<<2 * kL, 256>>>(Wsrc_ho, asrc_ho, Wdst_ho, adst_ho, Wedge_ho, aedge_ho,
                                  Wsrc_oh, asrc_oh, Wdst_oh, adst_oh, Wedge_oh, aedge_oh);
    k_wprep<<<dim3(16, 64), dim3(32, 8)>>>(Wsrc_ho, Wsrc_oh);

    // ---- 8 layers ----
    const float* cur_h = x_human;
    const float* cur_o = x_object;
    for (int l = 0; l < kL; l++) {
        float* nh = (l & 1) ? h1 : h0;
        float* no = (l & 1) ? o1 : o0;

        k_matvec2<<<kNH / 8, 256>>>(cur_h, vsrc + (0 * kL + l) * kD,
                                    vdst + (1 * kL + l) * kD, aSho, aDoh, kNH);
        k_matvec2<<<kNO / 8, 256>>>(cur_o, vdst + (0 * kL + l) * kD,
                                    vsrc + (1 * kL + l) * kD, aDho, aSoh, kNO);

        // GAT ho: humans -> objects
        k_aggregate<<<kNO / 8, 256>>>(off, eid, ei_ho, ea_ho, aSho, aDho,
                                      cur_h, ced + (0 * kL + l) * 2, agg, kNO);
        k_gemm_mma<<<GEMM_GRID, 512, GEMM_SMEM>>>(agg, wT + (long)(0 * kL + l) * 2 * kD * kD,
                                                  bias_ho + l * kD,
                                                  l ? cur_o : nullptr, no, kNO);
        // GAT oh: objects -> humans
        k_aggregate<<<kNH / 8, 256>>>(off + (kNH + 1), eid + kE, ei_oh, ea_oh, aSoh, aDoh,
                                      cur_o, ced + (1 * kL + l) * 2, agg, kNH);
        k_gemm_mma<<<GEMM_GRID, 512, GEMM_SMEM>>>(agg, wT + (long)(1 * kL + l) * 2 * kD * kD,
                                                  bias_oh + l * kD,
                                                  l ? cur_h : nullptr, nh, kNH);
        cur_h = nh;
        cur_o = no;
    }

    // ---- pooling ----
    cudaMemsetAsync(hsum, 0, sizeof(float) * kB * kD);
    cudaMemsetAsync(osum, 0, sizeof(float) * kB * kD);
    cudaMemsetAsync(esum, 0, sizeof(float) * kB * 32);
    cudaMemsetAsync(hcnt, 0, sizeof(float) * kB);
    cudaMemsetAsync(ocnt, 0, sizeof(float) * kB);
    cudaMemsetAsync(ecnt, 0, sizeof(float) * kB);
    k_pool_nodes<<<kNH, 256>>>(cur_h, hbatch, hsum, hcnt, kNH);
    k_pool_nodes<<<kNO, 256>>>(cur_o, obatch, osum, ocnt, kNO);
    k_pool_edges<<<EB, 256>>>(ea_ho, ei_ho, hbatch, W_emlp, b_emlp, esum, ecnt);

    // ---- classifier heads ----
    k_final<<<kB, 128>>>(hsum, hcnt, osum, ocnt, esum, ecnt,
                         W_p1, b_p1, W_p2, b_p2, (float*)d_out);
}

// round 6
// speedup vs baseline: 1.9384x; 1.2068x over previous
#include <cuda_runtime.h>
#include <cuda_bf16.h>
#include <cstdint>

static constexpr int kNH = 50000;
static constexpr int kNO = 50000;
static constexpr int kE  = 500000;
static constexpr int kD  = 256;
static constexpr int kL  = 8;
static constexpr int kB  = 512;
static constexpr int kC  = 117;

// ---------------- device scratch (static, no runtime alloc) ----------------
__device__ float g_h0[kNH * kD];
__device__ float g_h1[kNH * kD];
__device__ float g_o0[kNO * kD];
__device__ float g_o1[kNO * kD];
__device__ float g_agg0[kNO * kD];
__device__ float g_agg1[kNH * kD];

__device__ float g_aSho[kNH], g_aDoh[kNH], g_aDho[kNO], g_aSoh[kNO];

__device__ float g_vsrc[2 * kL * kD];
__device__ float g_vdst[2 * kL * kD];
__device__ float g_cedge[2 * kL * 2];

// W^T as bf16 hi/lo: [rel*8+layer][hi/lo][n=256][k=256]
__device__ __nv_bfloat16 g_wTb[2 * kL * 2 * kD * kD];

static constexpr int SCHUNK = 4096;
static constexpr int NCHUNK = (kNH + SCHUNK - 1) / SCHUNK;  // 13

__device__ int g_off[2 * (kNH + 1)];
__device__ int g_eid[2 * kE];
__device__ int g_cursor[2 * kNH];
__device__ int g_part[2 * NCHUNK];

__device__ float g_hsum[kB * kD], g_osum[kB * kD], g_esum[kB * 32];
__device__ float g_hcnt[kB], g_ocnt[kB], g_ecnt[kB];

__device__ __forceinline__ uint32_t pack2(__nv_bfloat16 a, __nv_bfloat16 b) {
    return (uint32_t)__bfloat16_as_ushort(a) | ((uint32_t)__bfloat16_as_ushort(b) << 16);
}

// ============================================================================
// small precompute: vsrc = Wsrc@asrc, vdst = Wdst@adst, cedge = Wedge@aedge
// ============================================================================
__global__ void k_precompute(
    const float* __restrict__ Wsrc0, const float* __restrict__ asrc0,
    const float* __restrict__ Wdst0, const float* __restrict__ adst0,
    const float* __restrict__ Wedge0, const float* __restrict__ aedge0,
    const float* __restrict__ Wsrc1, const float* __restrict__ asrc1,
    const float* __restrict__ Wdst1, const float* __restrict__ adst1,
    const float* __restrict__ Wedge1, const float* __restrict__ aedge1)
{
    int rel = blockIdx.x / kL;
    int l   = blockIdx.x % kL;
    const float* Wsrc  = rel ? Wsrc1  : Wsrc0;
    const float* asrc  = rel ? asrc1  : asrc0;
    const float* Wdst  = rel ? Wdst1  : Wdst0;
    const float* adst  = rel ? adst1  : adst0;
    const float* Wedge = rel ? Wedge1 : Wedge0;
    const float* aedge = rel ? aedge1 : aedge0;

    int i = threadIdx.x;
    float s1 = 0.f, s2 = 0.f;
    const float* wsr = Wsrc + (long)l * kD * kD + (long)i * kD;
    const float* wdr = Wdst + (long)l * kD * kD + (long)i * kD;
    const float* as  = asrc + l * kD;
    const float* ad  = adst + l * kD;
    for (int j = 0; j < kD; j++) { s1 += wsr[j] * as[j]; s2 += wdr[j] * ad[j]; }
    g_vsrc[(rel * kL + l) * kD + i] = s1;
    g_vdst[(rel * kL + l) * kD + i] = s2;
    if (i < 2) {
        float c = 0.f;
        const float* we = Wedge + (long)l * 2 * kD + (long)i * kD;
        const float* ae = aedge + l * kD;
        for (int j = 0; j < kD; j++) c += we[j] * ae[j];
        g_cedge[(rel * kL + l) * 2 + i] = c;
    }
}

// ---------------- transpose + bf16 hi/lo split of Wsrc weights ----------------
__global__ void k_wprep(const float* __restrict__ W_ho, const float* __restrict__ W_oh)
{
    int rl = blockIdx.x;                 // 0..15 = rel*8 + layer
    int rel = rl >> 3;
    const float* W = (rel ? W_oh : W_ho) + (long)(rl & 7) * kD * kD;
    int tile = blockIdx.y;               // 0..63
    int tk = (tile & 7) * 32, tn = (tile >> 3) * 32;
    __shared__ float s[32][33];
    int tx = threadIdx.x, ty = threadIdx.y;
    for (int yy = ty; yy < 32; yy += 8)
        s[yy][tx] = W[(long)(tk + yy) * kD + tn + tx];
    __syncthreads();
    __nv_bfloat16* outHi = g_wTb + (long)rl * 2 * kD * kD;
    __nv_bfloat16* outLo = outHi + kD * kD;
    for (int yy = ty; yy < 32; yy += 8) {
        float v = s[tx][yy];             // = W[tk+tx][tn+yy]
        __nv_bfloat16 h = __float2bfloat16(v);
        __nv_bfloat16 l = __float2bfloat16(v - __bfloat162float(h));
        outHi[(long)(tn + yy) * kD + tk + tx] = h;   // [n][k]
        outLo[(long)(tn + yy) * kD + tk + tx] = l;
    }
}

// ---------------- CSR build (dual-relation) ----------------
__global__ void k_hist(const int* __restrict__ d0, const int* __restrict__ d1,
                       int* __restrict__ cnt)
{
    int e = blockIdx.x * blockDim.x + threadIdx.x;
    if (e >= kE) return;
    int rel = blockIdx.y;
    const int* d = rel ? d1 : d0;
    atomicAdd(&cnt[rel * kNH + d[e]], 1);
}

__global__ void k_scan_part(const int* __restrict__ cnt, int* __restrict__ part)
{
    int rel = blockIdx.y, ch = blockIdx.x;
    const int* c = cnt + rel * kNH + ch * SCHUNK;
    int n = min(SCHUNK, kNH - ch * SCHUNK);
    int t = threadIdx.x, lane = t & 31, wid = t >> 5;
    int s = 0;
    for (int i = t; i < n; i += 256) s += c[i];
#pragma unroll
    for (int o = 16; o > 0; o >>= 1) s += __shfl_xor_sync(0xffffffffu, s, o);
    __shared__ int ws[8];
    if (lane == 0) ws[wid] = s;
    __syncthreads();
    if (t == 0) {
        int tot = 0;
        for (int k = 0; k < 8; k++) tot += ws[k];
        part[rel * NCHUNK + ch] = tot;
    }
}

__global__ void k_scan_mid(int* __restrict__ part)
{
    int rel = threadIdx.x;
    if (rel < 2) {
        int run = 0;
        for (int i = 0; i < NCHUNK; i++) {
            int v = part[rel * NCHUNK + i];
            part[rel * NCHUNK + i] = run;
            run += v;
        }
    }
}

__global__ void k_scan_apply(int* __restrict__ cnt, int* __restrict__ off,
                             const int* __restrict__ part)
{
    int rel = blockIdx.y, ch = blockIdx.x;
    int* cc = cnt + rel * kNH;
    int* oo = off + rel * (kNH + 1);
    int start = ch * SCHUNK;
    int n = min(SCHUNK, kNH - start);
    int t = threadIdx.x, lane = t & 31, wid = t >> 5;
    __shared__ int wsum[8];
    int carry = part[rel * NCHUNK + ch];
    for (int b0 = 0; b0 < n; b0 += 256) {
        int i = start + b0 + t;
        int c = (b0 + t < n) ? cc[i] : 0;
        int v = c;
#pragma unroll
        for (int o = 1; o < 32; o <<= 1) {
            int u = __shfl_up_sync(0xffffffffu, v, o);
            if (lane >= o) v += u;
        }
        if (lane == 31) wsum[wid] = v;
        __syncthreads();
        int wpre = 0, btot = 0;
#pragma unroll
        for (int k = 0; k < 8; k++) {
            int ws = wsum[k];
            if (k < wid) wpre += ws;
            btot += ws;
        }
        int excl = carry + (v - c) + wpre;
        if (b0 + t < n) { oo[i] = excl; cc[i] = excl; }
        carry += btot;
        __syncthreads();
    }
    if (t == 0 && ch == 0) oo[kNH] = kE;
}

__global__ void k_scatter(const int* __restrict__ d0, const int* __restrict__ d1,
                          int* __restrict__ cur, int* __restrict__ eid)
{
    int e = blockIdx.x * blockDim.x + threadIdx.x;
    if (e >= kE) return;
    int rel = blockIdx.y;
    const int* d = rel ? d1 : d0;
    int p = atomicAdd(&cur[rel * kNH + d[e]], 1);
    eid[rel * kE + p] = e;
}

// ---------------- fused dual matvec (both node sets) ----------------
__global__ void k_matvec2_dual(const float* __restrict__ xh, const float* __restrict__ xo,
                               const float* __restrict__ vh1, const float* __restrict__ vh2,
                               const float* __restrict__ vo1, const float* __restrict__ vo2,
                               float* __restrict__ aSho, float* __restrict__ aDoh,
                               float* __restrict__ aDho, float* __restrict__ aSoh)
{
    int gw = (blockIdx.x * blockDim.x + threadIdx.x) >> 5;
    int lane = threadIdx.x & 31;
    if (gw >= kNH + kNO) return;
    int rel = gw >= kNH;
    int w = rel ? gw - kNH : gw;
    const float* x  = rel ? xo  : xh;
    const float* v1 = rel ? vo1 : vh1;
    const float* v2 = rel ? vo2 : vh2;
    float* o1 = rel ? aDho : aSho;
    float* o2 = rel ? aSoh : aDoh;

    const float* xr = x + (long)w * kD;
    float s1 = 0.f, s2 = 0.f;
#pragma unroll
    for (int k = 0; k < 8; k++) {
        float xv = xr[lane + 32 * k];
        s1 += xv * v1[lane + 32 * k];
        s2 += xv * v2[lane + 32 * k];
    }
#pragma unroll
    for (int o = 16; o > 0; o >>= 1) {
        s1 += __shfl_xor_sync(0xffffffffu, s1, o);
        s2 += __shfl_xor_sync(0xffffffffu, s2, o);
    }
    if (lane == 0) { o1[w] = s1; o2[w] = s2; }
}

// ---------------- dual per-dst segment softmax + weighted gather-aggregate ----------------
__global__ void k_aggregate_dual(
    const int* __restrict__ off, const int* __restrict__ eid,
    const int* __restrict__ src0, const float* __restrict__ ea0,
    const float* __restrict__ aS0, const float* __restrict__ aD0,
    const float* __restrict__ x0, const float* __restrict__ ced0, float* __restrict__ agg0,
    const int* __restrict__ src1, const float* __restrict__ ea1,
    const float* __restrict__ aS1, const float* __restrict__ aD1,
    const float* __restrict__ x1, const float* __restrict__ ced1, float* __restrict__ agg1)
{
    int gw = (blockIdx.x * blockDim.x + threadIdx.x) >> 5;
    int lane = threadIdx.x & 31;
    if (gw >= kNO + kNH) return;
    int rel = gw >= kNO;
    int w = rel ? gw - kNO : gw;
    const int* o    = off + rel * (kNH + 1);
    const int* ei   = eid + rel * kE;
    const int* src  = rel ? src1 : src0;
    const float* ea = rel ? ea1 : ea0;
    const float* aS = rel ? aS1 : aS0;
    const float* aD = rel ? aD1 : aD0;
    const float* x  = rel ? x1 : x0;
    const float* ced = rel ? ced1 : ced0;
    float* agg = rel ? agg1 : agg0;

    int beg = o[w], end = o[w + 1];
    float c0 = ced[0], c1 = ced[1];
    float ad = aD[w];

    float m = -3.0e38f;
    for (int i = beg + lane; i < end; i += 32) {
        int e = ei[i];
        float lg = aS[src[e]] + ad + c0 * ea[2 * e] + c1 * ea[2 * e + 1];
        lg = lg > 0.f ? lg : 0.2f * lg;
        m = fmaxf(m, lg);
    }
#pragma unroll
    for (int o2 = 16; o2 > 0; o2 >>= 1) m = fmaxf(m, __shfl_xor_sync(0xffffffffu, m, o2));

    float den = 0.f;
    for (int i = beg + lane; i < end; i += 32) {
        int e = ei[i];
        float lg = aS[src[e]] + ad + c0 * ea[2 * e] + c1 * ea[2 * e + 1];
        lg = lg > 0.f ? lg : 0.2f * lg;
        den += expf(lg - m);
    }
#pragma unroll
    for (int o2 = 16; o2 > 0; o2 >>= 1) den += __shfl_xor_sync(0xffffffffu, den, o2);

    float inv = (den > 0.f) ? 1.f / den : 0.f;
    float acc[8] = {0.f, 0.f, 0.f, 0.f, 0.f, 0.f, 0.f, 0.f};
    for (int i = beg; i < end; i++) {
        int e = ei[i];
        int s = src[e];
        float lg = aS[s] + ad + c0 * ea[2 * e] + c1 * ea[2 * e + 1];
        lg = lg > 0.f ? lg : 0.2f * lg;
        float wt = expf(lg - m) * inv;
        const float* xr = x + (long)s * kD;
#pragma unroll
        for (int k = 0; k < 8; k++) acc[k] += wt * xr[lane + 32 * k];
    }
    float* ar = agg + (long)w * kD;
#pragma unroll
    for (int k = 0; k < 8; k++) ar[lane + 32 * k] = acc[k];
}

// ============================================================================
// mma.sync bf16 GEMM (3xBF16): out = relu(A@W + bias) (+ prev)
// A:[M,256] fp32 (split in-kernel), WTb hi/lo [256n][256k] bf16 pre-split.
// CTA tile 128M x 128N, 16 warps (32x32 each), dual relation via blockIdx.z.
// ============================================================================
static constexpr int HSTRIDE = 40;  // halfs per smem row (32 + 8 pad) -> conflict-free frags
static constexpr int GEMM_SMEM = 4 * 128 * HSTRIDE * 2;  // 40960 B

__device__ __forceinline__ void mma_bf16(float* c, const uint32_t* a, const uint32_t* b) {
    asm volatile(
        "mma.sync.aligned.m16n8k16.row.col.f32.bf16.bf16.f32 "
        "{%0,%1,%2,%3}, {%4,%5,%6,%7}, {%8,%9}, {%0,%1,%2,%3};\n"
        : "+f"(c[0]), "+f"(c[1]), "+f"(c[2]), "+f"(c[3])
        : "r"(a[0]), "r"(a[1]), "r"(a[2]), "r"(a[3]), "r"(b[0]), "r"(b[1]));
}

__global__ void __launch_bounds__(512) k_gemm_mma(
    const float* __restrict__ A0, const float* __restrict__ A1,
    const __nv_bfloat16* __restrict__ WT0, const __nv_bfloat16* __restrict__ WT1,
    const float* __restrict__ bias0, const float* __restrict__ bias1,
    const float* __restrict__ prev0, const float* __restrict__ prev1,
    float* __restrict__ out0, float* __restrict__ out1, int M)
{
    extern __shared__ __nv_bfloat16 smh[];
    __nv_bfloat16* sAhi = smh;
    __nv_bfloat16* sAlo = smh + 128 * HSTRIDE;
    __nv_bfloat16* sBhi = smh + 2 * 128 * HSTRIDE;
    __nv_bfloat16* sBlo = smh + 3 * 128 * HSTRIDE;

    const int z = blockIdx.z;
    const float* A = z ? A1 : A0;
    const __nv_bfloat16* WT = z ? WT1 : WT0;
    const float* bias = z ? bias1 : bias0;
    const float* prev = z ? prev1 : prev0;
    float* out = z ? out1 : out0;

    const int tid = threadIdx.x;
    const int w = tid >> 5, lane = tid & 31;
    const int wm = w & 3, wn = w >> 2;       // 4x4 warp grid, each warp 32m x 32n
    const int grp = lane >> 2, qt = lane & 3;
    const int mBase = blockIdx.y * 128;
    const int nBase = blockIdx.x * 128;

    const __nv_bfloat16* WThi = WT + (long)nBase * kD;
    const __nv_bfloat16* WTlo = WT + (long)kD * kD + (long)nBase * kD;

    float acc[2][4][4];
#pragma unroll
    for (int i = 0; i < 2; i++)
#pragma unroll
        for (int j = 0; j < 4; j++)
#pragma unroll
            for (int q = 0; q < 4; q++) acc[i][j][q] = 0.f;

    for (int c = 0; c < 8; c++) {
        // A chunk 128x32 fp32 -> bf16 hi/lo
#pragma unroll
        for (int it = 0; it < 2; it++) {
            int idx = tid + it * 512;            // 0..1023
            int r = idx >> 3, q = idx & 7;
            int gm = mBase + r;
            float4 v = (gm < M) ? *(const float4*)&A[(long)gm * kD + c * 32 + q * 4]
                                : make_float4(0.f, 0.f, 0.f, 0.f);
            __nv_bfloat16 hx = __float2bfloat16(v.x), hy = __float2bfloat16(v.y);
            __nv_bfloat16 hz = __float2bfloat16(v.z), hw = __float2bfloat16(v.w);
            __nv_bfloat16 lx = __float2bfloat16(v.x - __bfloat162float(hx));
            __nv_bfloat16 ly = __float2bfloat16(v.y - __bfloat162float(hy));
            __nv_bfloat16 lz = __float2bfloat16(v.z - __bfloat162float(hz));
            __nv_bfloat16 lw = __float2bfloat16(v.w - __bfloat162float(hw));
            uint2 hv, lv;
            hv.x = pack2(hx, hy); hv.y = pack2(hz, hw);
            lv.x = pack2(lx, ly); lv.y = pack2(lz, lw);
            *(uint2*)&sAhi[r * HSTRIDE + q * 4] = hv;
            *(uint2*)&sAlo[r * HSTRIDE + q * 4] = lv;
        }
        // B chunk 128n x 32k bf16 (pre-split)
#pragma unroll
        for (int it = 0; it < 2; it++) {
            int idx = tid + it * 512;
            int n = idx >> 3, q = idx & 7;
            *(uint2*)&sBhi[n * HSTRIDE + q * 4] =
                *(const uint2*)&WThi[(long)n * kD + c * 32 + q * 4];
            *(uint2*)&sBlo[n * HSTRIDE + q * 4] =
                *(const uint2*)&WTlo[(long)n * kD + c * 32 + q * 4];
        }
        __syncthreads();

#pragma unroll
        for (int ks = 0; ks < 2; ks++) {
            int kb = ks * 16;
            uint32_t ahi[2][4], alo[2][4], bhi[4][2], blo[4][2];
#pragma unroll
            for (int i = 0; i < 2; i++) {
                int ra = (wm * 32 + i * 16 + grp) * HSTRIDE + kb + qt * 2;
                ahi[i][0] = *(const uint32_t*)&sAhi[ra];
                ahi[i][1] = *(const uint32_t*)&sAhi[ra + 8 * HSTRIDE];
                ahi[i][2] = *(const uint32_t*)&sAhi[ra + 8];
                ahi[i][3] = *(const uint32_t*)&sAhi[ra + 8 * HSTRIDE + 8];
                alo[i][0] = *(const uint32_t*)&sAlo[ra];
                alo[i][1] = *(const uint32_t*)&sAlo[ra + 8 * HSTRIDE];
                alo[i][2] = *(const uint32_t*)&sAlo[ra + 8];
                alo[i][3] = *(const uint32_t*)&sAlo[ra + 8 * HSTRIDE + 8];
            }
#pragma unroll
            for (int j = 0; j < 4; j++) {
                int rb = (wn * 32 + j * 8 + grp) * HSTRIDE + kb + qt * 2;
                bhi[j][0] = *(const uint32_t*)&sBhi[rb];
                bhi[j][1] = *(const uint32_t*)&sBhi[rb + 8];
                blo[j][0] = *(const uint32_t*)&sBlo[rb];
                blo[j][1] = *(const uint32_t*)&sBlo[rb + 8];
            }
#pragma unroll
            for (int i = 0; i < 2; i++)
#pragma unroll
                for (int j = 0; j < 4; j++) {
                    mma_bf16(acc[i][j], ahi[i], bhi[j]);
                    mma_bf16(acc[i][j], ahi[i], blo[j]);
                    mma_bf16(acc[i][j], alo[i], bhi[j]);
                }
        }
        __syncthreads();
    }

    // epilogue
#pragma unroll
    for (int i = 0; i < 2; i++) {
#pragma unroll
        for (int h = 0; h < 2; h++) {
            int row = mBase + wm * 32 + i * 16 + grp + h * 8;
            if (row >= M) continue;
#pragma unroll
            for (int j = 0; j < 4; j++) {
                int col = nBase + wn * 32 + j * 8 + qt * 2;
                float v0 = acc[i][j][h * 2 + 0] + bias[col];
                float v1 = acc[i][j][h * 2 + 1] + bias[col + 1];
                v0 = fmaxf(v0, 0.f);
                v1 = fmaxf(v1, 0.f);
                if (prev) {
                    float2 pv = *(const float2*)&prev[(long)row * kD + col];
                    v0 += pv.x; v1 += pv.y;
                }
                float2 o; o.x = v0; o.y = v1;
                *(float2*)&out[(long)row * kD + col] = o;
            }
        }
    }
}

// ---------------- pooling ----------------
__global__ void k_pool_nodes(const float* __restrict__ x, const int* __restrict__ batch,
                             float* __restrict__ sum, float* __restrict__ cnt, int N)
{
    long idx = (long)blockIdx.x * blockDim.x + threadIdx.x;
    if (idx >= (long)N * kD) return;
    int n = (int)(idx >> 8);
    int d = (int)(idx & 255);
    int b = batch[n];
    atomicAdd(&sum[b * kD + d], x[idx]);
    if (d == 0) atomicAdd(&cnt[b], 1.f);
}

__global__ void k_pool_edges(const float* __restrict__ ea, const int* __restrict__ src,
                             const int* __restrict__ hbatch,
                             const float* __restrict__ Wm, const float* __restrict__ bm,
                             float* __restrict__ esum, float* __restrict__ ecnt)
{
    int e = blockIdx.x * blockDim.x + threadIdx.x;
    if (e >= kE) return;
    float e0 = ea[2 * e], e1 = ea[2 * e + 1];
    int b = hbatch[src[e]];
    atomicAdd(&ecnt[b], 1.f);
#pragma unroll
    for (int j = 0; j < 32; j++) {
        float v = fmaxf(e0 * Wm[j] + e1 * Wm[32 + j] + bm[j], 0.f);
        atomicAdd(&esum[b * 32 + j], v);
    }
}

// ---------------- final: graph emb -> 2 softmax heads ----------------
__global__ void k_final(const float* __restrict__ hsum, const float* __restrict__ hcnt,
                        const float* __restrict__ osum, const float* __restrict__ ocnt,
                        const float* __restrict__ esum, const float* __restrict__ ecnt,
                        const float* __restrict__ Wp1, const float* __restrict__ bp1,
                        const float* __restrict__ Wp2, const float* __restrict__ bp2,
                        float* __restrict__ out)
{
    __shared__ float emb[2 * kD + 32];
    __shared__ float red[128];
    int b = blockIdx.x, t = threadIdx.x;
    float hc = fmaxf(hcnt[b], 1.f), oc = fmaxf(ocnt[b], 1.f), ec = fmaxf(ecnt[b], 1.f);
    for (int k = t; k < kD; k += 128) {
        emb[k]      = hsum[b * kD + k] / hc;
        emb[kD + k] = osum[b * kD + k] / oc;
    }
    for (int k = t; k < 32; k += 128) emb[2 * kD + k] = esum[b * 32 + k] / ec;
    __syncthreads();

    for (int head = 0; head < 2; head++) {
        const float* W  = head ? Wp2 : Wp1;
        const float* bb = head ? bp2 : bp1;
        float v = -3.0e38f;
        if (t < kC) {
            v = bb[t];
            for (int k = 0; k < 2 * kD + 32; k++) v += emb[k] * W[k * kC + t];
        }
        red[t] = v;
        __syncthreads();
        for (int s = 64; s > 0; s >>= 1) {
            if (t < s) red[t] = fmaxf(red[t], red[t + s]);
            __syncthreads();
        }
        float mx = red[0];
        __syncthreads();
        float ex = (t < kC) ? expf(v - mx) : 0.f;
        red[t] = ex;
        __syncthreads();
        for (int s = 64; s > 0; s >>= 1) {
            if (t < s) red[t] += red[t + s];
            __syncthreads();
        }
        float sm = red[0];
        __syncthreads();
        if (t < kC) out[(b * 2 + head) * kC + t] = ex / sm;
    }
}

// ---------------- launch ----------------
extern "C" void kernel_launch(void* const* d_in, const int* in_sizes, int n_in,
                              void* d_out, int out_size)
{
    const float* x_human = (const float*)d_in[0];
    const float* x_object = (const float*)d_in[1];
    const int* ei_ho = (const int*)d_in[2];
    const int* ei_oh = (const int*)d_in[3];
    const float* ea_ho = (const float*)d_in[4];
    const float* ea_oh = (const float*)d_in[5];
    const int* hbatch = (const int*)d_in[6];
    const int* obatch = (const int*)d_in[7];
    const float* Wsrc_ho = (const float*)d_in[8];
    const float* Wdst_ho = (const float*)d_in[9];
    const float* asrc_ho = (const float*)d_in[10];
    const float* adst_ho = (const float*)d_in[11];
    const float* Wedge_ho = (const float*)d_in[12];
    const float* aedge_ho = (const float*)d_in[13];
    const float* bias_ho = (const float*)d_in[14];
    const float* Wsrc_oh = (const float*)d_in[15];
    const float* Wdst_oh = (const float*)d_in[16];
    const float* asrc_oh = (const float*)d_in[17];
    const float* adst_oh = (const float*)d_in[18];
    const float* Wedge_oh = (const float*)d_in[19];
    const float* aedge_oh = (const float*)d_in[20];
    const float* bias_oh = (const float*)d_in[21];
    const float* W_emlp = (const float*)d_in[22];
    const float* b_emlp = (const float*)d_in[23];
    const float* W_p1 = (const float*)d_in[24];
    const float* b_p1 = (const float*)d_in[25];
    const float* W_p2 = (const float*)d_in[26];
    const float* b_p2 = (const float*)d_in[27];

    float *h0, *h1, *o0, *o1, *agg0, *agg1;
    float *aSho, *aDoh, *aDho, *aSoh, *vsrc, *vdst, *ced;
    float *hsum, *osum, *esum, *hcnt, *ocnt, *ecnt;
    __nv_bfloat16* wTb;
    int *off, *eid, *cur, *part;
    cudaGetSymbolAddress((void**)&h0, g_h0);
    cudaGetSymbolAddress((void**)&h1, g_h1);
    cudaGetSymbolAddress((void**)&o0, g_o0);
    cudaGetSymbolAddress((void**)&o1, g_o1);
    cudaGetSymbolAddress((void**)&agg0, g_agg0);
    cudaGetSymbolAddress((void**)&agg1, g_agg1);
    cudaGetSymbolAddress((void**)&aSho, g_aSho);
    cudaGetSymbolAddress((void**)&aDoh, g_aDoh);
    cudaGetSymbolAddress((void**)&aDho, g_aDho);
    cudaGetSymbolAddress((void**)&aSoh, g_aSoh);
    cudaGetSymbolAddress((void**)&vsrc, g_vsrc);
    cudaGetSymbolAddress((void**)&vdst, g_vdst);
    cudaGetSymbolAddress((void**)&ced, g_cedge);
    cudaGetSymbolAddress((void**)&wTb, g_wTb);
    cudaGetSymbolAddress((void**)&off, g_off);
    cudaGetSymbolAddress((void**)&eid, g_eid);
    cudaGetSymbolAddress((void**)&cur, g_cursor);
    cudaGetSymbolAddress((void**)&part, g_part);
    cudaGetSymbolAddress((void**)&hsum, g_hsum);
    cudaGetSymbolAddress((void**)&osum, g_osum);
    cudaGetSymbolAddress((void**)&esum, g_esum);
    cudaGetSymbolAddress((void**)&hcnt, g_hcnt);
    cudaGetSymbolAddress((void**)&ocnt, g_ocnt);
    cudaGetSymbolAddress((void**)&ecnt, g_ecnt);

    cudaFuncSetAttribute(k_gemm_mma, cudaFuncAttributeMaxDynamicSharedMemorySize, GEMM_SMEM);

    const int EB = (kE + 255) / 256;
    const dim3 GEMM_GRID(2, (kNH + 127) / 128, 2);

    // ---- CSR build for both relations ----
    cudaMemsetAsync(cur, 0, sizeof(int) * 2 * kNH);
    k_hist<<<dim3(EB, 2), 256>>>(ei_ho + kE, ei_oh + kE, cur);
    k_scan_part<<<dim3(NCHUNK, 2), 256>>>(cur, part);
    k_scan_mid<<<1, 32>>>(part);
    k_scan_apply<<<dim3(NCHUNK, 2), 256>>>(cur, off, part);
    k_scatter<<<dim3(EB, 2), 256>>>(ei_ho + kE, ei_oh + kE, cur, eid);

    // ---- per-layer precompute ----
    k_precompute<<<2 * kL, 256>>>(Wsrc_ho, asrc_ho, Wdst_ho, adst_ho, Wedge_ho, aedge_ho,
                                  Wsrc_oh, asrc_oh, Wdst_oh, adst_oh, Wedge_oh, aedge_oh);
    k_wprep<<<dim3(16, 64), dim3(32, 8)>>>(Wsrc_ho, Wsrc_oh);

    // ---- 8 layers ----
    const float* cur_h = x_human;
    const float* cur_o = x_object;
    for (int l = 0; l < kL; l++) {
        float* nh = (l & 1) ? h1 : h0;
        float* no = (l & 1) ? o1 : o0;

        k_matvec2_dual<<<(kNH + kNO) / 8, 256>>>(
            cur_h, cur_o,
            vsrc + (0 * kL + l) * kD, vdst + (1 * kL + l) * kD,
            vdst + (0 * kL + l) * kD, vsrc + (1 * kL + l) * kD,
            aSho, aDoh, aDho, aSoh);

        k_aggregate_dual<<<(kNO + kNH) / 8, 256>>>(
            off, eid,
            ei_ho, ea_ho, aSho, aDho, cur_h, ced + (0 * kL + l) * 2, agg0,
            ei_oh, ea_oh, aSoh, aDoh, cur_o, ced + (1 * kL + l) * 2, agg1);

        k_gemm_mma<<<GEMM_GRID, 512, GEMM_SMEM>>>(
            agg0, agg1,
            wTb + (long)(0 * kL + l) * 2 * kD * kD, wTb + (long)(1 * kL + l) * 2 * kD * kD,
            bias_ho + l * kD, bias_oh + l * kD,
            l ? cur_o : nullptr, l ? cur_h : nullptr,
            no, nh, kNO);

        cur_h = nh;
        cur_o = no;
    }

    // ---- pooling ----
    cudaMemsetAsync(hsum, 0, sizeof(float) * kB * kD);
    cudaMemsetAsync(osum, 0, sizeof(float) * kB * kD);
    cudaMemsetAsync(esum, 0, sizeof(float) * kB * 32);
    cudaMemsetAsync(hcnt, 0, sizeof(float) * kB);
    cudaMemsetAsync(ocnt, 0, sizeof(float) * kB);
    cudaMemsetAsync(ecnt, 0, sizeof(float) * kB);
    k_pool_nodes<<<kNH, 256>>>(cur_h, hbatch, hsum, hcnt, kNH);
    k_pool_nodes<<<kNO, 256>>>(cur_o, obatch, osum, ocnt, kNO);
    k_pool_edges<<<EB, 256>>>(ea_ho, ei_ho, hbatch, W_emlp, b_emlp, esum, ecnt);

    // ---- classifier heads ----
    k_final<<<kB, 128>>>(hsum, hcnt, osum, ocnt, esum, ecnt,
                         W_p1, b_p1, W_p2, b_p2, (float*)d_out);
}